// round 1
// baseline (speedup 1.0000x reference)
#include <cuda_runtime.h>
#include <cuda_bf16.h>
#include <math.h>

#define N_NODES 50000
#define D 128
#define MAXE 800000
#define NB_STATS 240
#define BN_EPS 1e-5f

// ---------------- scratch (device globals; no allocation allowed) ----------
__device__ float g_hlin[N_NODES * D];       // GEMM output (pre-aggregation)
__device__ float g_agg [N_NODES * D];       // aggregated conv output
__device__ float g_cat [N_NODES * 3 * D];   // [h1|h2|h3] concatenated, stride 384
__device__ float g_dinv[N_NODES];
__device__ int   g_deg [N_NODES];
__device__ int   g_cur [N_NODES];
__device__ int   g_off [N_NODES + 1];
__device__ int   g_csr [MAXE];
__device__ float g_part [NB_STATS * D];
__device__ float g_part2[NB_STATS * D];
__device__ float g_scale[D];
__device__ float g_shift[D];

// ---------------- CSR build -------------------------------------------------
__global__ void zero_init_kernel() {
    int i = blockIdx.x * blockDim.x + threadIdx.x;
    if (i < N_NODES) { g_deg[i] = 0; g_cur[i] = 0; }
}

__global__ void hist_kernel(const int* __restrict__ col, int E) {
    int e = blockIdx.x * blockDim.x + threadIdx.x;
    if (e < E) atomicAdd(&g_deg[col[e]], 1);
}

// single-block exclusive scan of g_deg -> g_off (g_off[N]=E)
__global__ void scan_kernel(int n) {
    __shared__ int wsum[32];
    const int tid  = threadIdx.x;                 // 1024 threads
    const int ipt  = (n + 1023) >> 10;
    int start = tid * ipt;
    int end   = min(start + ipt, n);
    int s = 0;
    for (int i = start; i < end; i++) s += g_deg[i];
    int lane = tid & 31, w = tid >> 5;
    int v = s;
    #pragma unroll
    for (int d = 1; d < 32; d <<= 1) { int t = __shfl_up_sync(0xffffffffu, v, d); if (lane >= d) v += t; }
    if (lane == 31) wsum[w] = v;
    __syncthreads();
    if (w == 0) {
        int x = wsum[lane];
        #pragma unroll
        for (int d = 1; d < 32; d <<= 1) { int t = __shfl_up_sync(0xffffffffu, x, d); if (lane >= d) x += t; }
        wsum[lane] = x;
    }
    __syncthreads();
    int run = v - s + (w > 0 ? wsum[w - 1] : 0);  // exclusive prefix for this thread
    for (int i = start; i < end; i++) { g_off[i] = run; run += g_deg[i]; }
    if (end == n) g_off[n] = run;
}

__global__ void dinv_kernel() {
    int i = blockIdx.x * blockDim.x + threadIdx.x;
    if (i < N_NODES) g_dinv[i] = rsqrtf((float)(g_deg[i] + 1));  // +1: self loop
}

__global__ void fill_csr_kernel(const int* __restrict__ row,
                                const int* __restrict__ col, int E) {
    int e = blockIdx.x * blockDim.x + threadIdx.x;
    if (e < E) {
        int c = col[e];
        int p = atomicAdd(&g_cur[c], 1);
        g_csr[g_off[c] + p] = row[e];
    }
}

// ---------------- sgemm: [M,128] @ [128,128] -> g_hlin ---------------------
// BM=BN=128, BK=16, 256 threads, 8x8 register tile.
// If cat_off >= 0, A = g_cat + cat_off (device-side; host can't form the address).
__global__ __launch_bounds__(256)
void sgemm_kernel(const float* __restrict__ Aext, int lda, int cat_off,
                  const float* __restrict__ W, int M) {
    const float* A = (cat_off >= 0) ? (g_cat + cat_off) : Aext;
    __shared__ float As[16][128];
    __shared__ float Ws[16][128];
    const int tid  = threadIdx.x;
    const int brow = blockIdx.x * 128;
    const int tr   = (tid >> 4) * 8;
    const int tc   = (tid & 15) * 8;
    float acc[8][8];
    #pragma unroll
    for (int i = 0; i < 8; i++)
        #pragma unroll
        for (int j = 0; j < 8; j++) acc[i][j] = 0.f;

    const int a_m  = tid >> 2;           // 0..63
    const int a_k4 = (tid & 3) * 4;      // 0,4,8,12
    const int w_k  = tid >> 5;           // 0..7
    const int w_n  = (tid & 31) * 4;

    for (int k0 = 0; k0 < 128; k0 += 16) {
        #pragma unroll
        for (int p = 0; p < 2; p++) {
            int m  = a_m + p * 64;
            int gm = brow + m;
            float4 v = make_float4(0.f, 0.f, 0.f, 0.f);
            if (gm < M) v = *(const float4*)(A + (long)gm * lda + k0 + a_k4);
            As[a_k4 + 0][m] = v.x;
            As[a_k4 + 1][m] = v.y;
            As[a_k4 + 2][m] = v.z;
            As[a_k4 + 3][m] = v.w;
        }
        #pragma unroll
        for (int p = 0; p < 2; p++) {
            int k = w_k + p * 8;
            *(float4*)&Ws[k][w_n] = *(const float4*)(W + (k0 + k) * 128 + w_n);
        }
        __syncthreads();
        #pragma unroll
        for (int k = 0; k < 16; k++) {
            float am[8], wn[8];
            #pragma unroll
            for (int i = 0; i < 8; i++) am[i] = As[k][tr + i];
            #pragma unroll
            for (int j = 0; j < 8; j++) wn[j] = Ws[k][tc + j];
            #pragma unroll
            for (int i = 0; i < 8; i++)
                #pragma unroll
                for (int j = 0; j < 8; j++)
                    acc[i][j] = fmaf(am[i], wn[j], acc[i][j]);
        }
        __syncthreads();
    }
    #pragma unroll
    for (int i = 0; i < 8; i++) {
        int gm = brow + tr + i;
        if (gm < M) {
            #pragma unroll
            for (int j = 0; j < 8; j += 4)
                *(float4*)(g_hlin + (long)gm * 128 + tc + j) =
                    make_float4(acc[i][j], acc[i][j + 1], acc[i][j + 2], acc[i][j + 3]);
        }
    }
}

// ---------------- aggregation: agg = D^-1/2 (A+I) D^-1/2 hlin + b ----------
// one block (128 threads = feature dim) per destination node
__global__ __launch_bounds__(128)
void agg_kernel(const float* __restrict__ b) {
    __shared__ int   sr[128];
    __shared__ float sd[128];
    const int c = blockIdx.x;
    const int t = threadIdx.x;
    const float dc = g_dinv[c];
    float acc = dc * g_hlin[(long)c * D + t];   // self loop term
    const int s = g_off[c], e = g_off[c + 1];
    for (int base = s; base < e; base += 128) {
        int nchunk = min(128, e - base);
        if (t < nchunk) {
            int r = g_csr[base + t];
            sr[t] = r;
            sd[t] = g_dinv[r];
        }
        __syncthreads();
        for (int i = 0; i < nchunk; i++)
            acc = fmaf(sd[i], g_hlin[(long)sr[i] * D + t], acc);
        __syncthreads();
    }
    g_agg[(long)c * D + t] = fmaf(dc, acc, b[t]);
}

// ---------------- batch norm (training mode) --------------------------------
__global__ void bn_stats_kernel() {
    const int t = threadIdx.x;           // 128
    float s = 0.f, s2 = 0.f;
    for (int n = blockIdx.x; n < N_NODES; n += gridDim.x) {
        float v = g_agg[(long)n * D + t];
        s += v; s2 += v * v;
    }
    g_part [blockIdx.x * D + t] = s;
    g_part2[blockIdx.x * D + t] = s2;
}

__global__ void bn_finalize_kernel(const float* __restrict__ g,
                                   const float* __restrict__ be) {
    const int t = threadIdx.x;           // 128
    float s = 0.f, s2 = 0.f;
    for (int i = 0; i < NB_STATS; i++) { s += g_part[i * D + t]; s2 += g_part2[i * D + t]; }
    float m   = s  / (float)N_NODES;
    float var = s2 / (float)N_NODES - m * m;
    float sc  = g[t] * rsqrtf(var + BN_EPS);
    g_scale[t] = sc;
    g_shift[t] = fmaf(-m, sc, be[t]);
}

__global__ void bn_relu_kernel(int loff) {
    int i = blockIdx.x * blockDim.x + threadIdx.x;    // over N * 32 float4s
    if (i >= N_NODES * (D / 4)) return;
    int n = i >> 5;
    int v = (i & 31) * 4;
    float4 a  = *(const float4*)&g_agg[(long)n * D + v];
    float4 sc = *(const float4*)&g_scale[v];
    float4 sh = *(const float4*)&g_shift[v];
    float4 r;
    r.x = fmaxf(0.f, fmaf(a.x, sc.x, sh.x));
    r.y = fmaxf(0.f, fmaf(a.y, sc.y, sh.y));
    r.z = fmaxf(0.f, fmaf(a.z, sc.z, sh.z));
    r.w = fmaxf(0.f, fmaf(a.w, sc.w, sh.w));
    *(float4*)&g_cat[(long)n * 384 + loff + v] = r;
}

// ---------------- final: out = cat @ Wf + bf  ([N,384] @ [384,10]) ----------
__global__ __launch_bounds__(320)
void final_kernel(const float* __restrict__ Wf, const float* __restrict__ bf,
                  float* __restrict__ out, int M) {
    __shared__ float wf_s[384 * 10];
    __shared__ float bf_s[10];
    const int tid = threadIdx.x;         // 320
    for (int i = tid; i < 3840; i += 320) wf_s[i] = Wf[i];
    if (tid < 10) bf_s[tid] = bf[tid];
    __syncthreads();
    const int ln = tid / 10;
    const int c  = tid - ln * 10;
    const int gn = blockIdx.x * 32 + ln;
    if (gn >= M) return;
    const float* hrow = g_cat + (long)gn * 384;
    float acc = bf_s[c];
    #pragma unroll 8
    for (int t = 0; t < 384; t++)
        acc = fmaf(__ldg(hrow + t), wf_s[t * 10 + c], acc);
    out[gn * 10 + c] = acc;
}

// ---------------- launch -----------------------------------------------------
extern "C" void kernel_launch(void* const* d_in, const int* in_sizes, int n_in,
                              void* d_out, int out_size) {
    const float* x   = (const float*)d_in[0];
    const int*   ei  = (const int*)  d_in[1];
    const int    E   = in_sizes[1] / 2;
    const float* W1  = (const float*)d_in[2];
    const float* b1  = (const float*)d_in[3];
    const float* W2  = (const float*)d_in[4];
    const float* b2  = (const float*)d_in[5];
    const float* W3  = (const float*)d_in[6];
    const float* b3  = (const float*)d_in[7];
    const float* g1  = (const float*)d_in[8];
    const float* be1 = (const float*)d_in[9];
    const float* g2  = (const float*)d_in[10];
    const float* be2 = (const float*)d_in[11];
    const float* g3  = (const float*)d_in[12];
    const float* be3 = (const float*)d_in[13];
    const float* Wf  = (const float*)d_in[14];
    const float* bf  = (const float*)d_in[15];
    float* out = (float*)d_out;

    const int* row = ei;
    const int* col = ei + E;

    // --- build normalized CSR (by destination) once per launch ---
    zero_init_kernel<<<(N_NODES + 255) / 256, 256>>>();
    hist_kernel<<<(E + 255) / 256, 256>>>(col, E);
    scan_kernel<<<1, 1024>>>(N_NODES);
    dinv_kernel<<<(N_NODES + 255) / 256, 256>>>();
    fill_csr_kernel<<<(E + 255) / 256, 256>>>(row, col, E);

    const int gemm_grid = (N_NODES + 127) / 128;   // 391
    const int br_grid   = (N_NODES * (D / 4) + 255) / 256;

    const float* Wl[3]  = {W1, W2, W3};
    const float* bl[3]  = {b1, b2, b3};
    const float* gl[3]  = {g1, g2, g3};
    const float* bel[3] = {be1, be2, be3};

    for (int l = 0; l < 3; l++) {
        if (l == 0)
            sgemm_kernel<<<gemm_grid, 256>>>(x, 128, -1, Wl[l], N_NODES);
        else
            sgemm_kernel<<<gemm_grid, 256>>>(nullptr, 384, (l - 1) * 128, Wl[l], N_NODES);
        agg_kernel<<<N_NODES, 128>>>(bl[l]);
        bn_stats_kernel<<<NB_STATS, 128>>>();
        bn_finalize_kernel<<<1, 128>>>(gl[l], bel[l]);
        bn_relu_kernel<<<br_grid, 256>>>(l * 128);
    }

    final_kernel<<<(N_NODES + 31) / 32, 320>>>(Wf, bf, out, N_NODES);
}

// round 2
// speedup vs baseline: 1.4723x; 1.4723x over previous
#include <cuda_runtime.h>
#include <cuda_bf16.h>
#include <math.h>

#define N_NODES 50000
#define D 128
#define MAXE 800000
#define BN_EPS 1e-5f
#define NBS_BLK 120
#define NBS_WARPS (NBS_BLK * 16)   // 1920 partial slots

// ---------------- scratch (device globals; no allocation allowed) ----------
__device__ float g_hlin[N_NODES * D];          // GEMM output (pre-aggregation)
__device__ float g_agg [3][N_NODES * D];       // raw conv outputs per layer
__device__ float g_dinv[N_NODES];
__device__ int   g_deg [N_NODES];
__device__ int   g_cur [N_NODES];
__device__ int   g_off [N_NODES + 1];
__device__ int   g_csr [MAXE];
__device__ float g_part [NBS_WARPS * D];
__device__ float g_part2[NBS_WARPS * D];
__device__ float g_scaleL[3 * D];
__device__ float g_shiftL[3 * D];

// ---------------- CSR build -------------------------------------------------
__global__ void zero_init_kernel() {
    int i = blockIdx.x * blockDim.x + threadIdx.x;
    if (i < N_NODES) { g_deg[i] = 0; g_cur[i] = 0; }
}

__global__ void hist_kernel(const int* __restrict__ col, int E) {
    int e = blockIdx.x * blockDim.x + threadIdx.x;
    if (e < E) atomicAdd(&g_deg[col[e]], 1);
}

// single-block exclusive scan of g_deg -> g_off
__global__ void scan_kernel(int n) {
    __shared__ int wsum[32];
    const int tid = threadIdx.x;                 // 1024
    const int ipt = (n + 1023) >> 10;
    int start = tid * ipt;
    int end   = min(start + ipt, n);
    int s = 0;
    for (int i = start; i < end; i++) s += g_deg[i];
    int lane = tid & 31, w = tid >> 5;
    int v = s;
    #pragma unroll
    for (int d = 1; d < 32; d <<= 1) { int t = __shfl_up_sync(0xffffffffu, v, d); if (lane >= d) v += t; }
    if (lane == 31) wsum[w] = v;
    __syncthreads();
    if (w == 0) {
        int x = wsum[lane];
        #pragma unroll
        for (int d = 1; d < 32; d <<= 1) { int t = __shfl_up_sync(0xffffffffu, x, d); if (lane >= d) x += t; }
        wsum[lane] = x;
    }
    __syncthreads();
    int run = v - s + (w > 0 ? wsum[w - 1] : 0);
    for (int i = start; i < end; i++) { g_off[i] = run; run += g_deg[i]; }
    if (end == n) g_off[n] = run;
}

__global__ void dinv_kernel() {
    int i = blockIdx.x * blockDim.x + threadIdx.x;
    if (i < N_NODES) g_dinv[i] = rsqrtf((float)(g_deg[i] + 1));
}

__global__ void fill_csr_kernel(const int* __restrict__ row,
                                const int* __restrict__ col, int E) {
    int e = blockIdx.x * blockDim.x + threadIdx.x;
    if (e < E) {
        int c = col[e];
        int p = atomicAdd(&g_cur[c], 1);
        g_csr[g_off[c] + p] = row[e];
    }
}

// ---------------- sgemm: relu(bn(prev)) @ W -> g_hlin -----------------------
// 128x128 tile, BK=16, 256 threads, 8x8 reg tile, double-buffered smem.
// layer==0: A = x (raw). layer>0: A = g_agg[layer-1] with BN+relu applied on load.
__global__ __launch_bounds__(256)
void sgemm_kernel(const float* __restrict__ x, const float* __restrict__ W,
                  int layer, int M) {
    const float* __restrict__ A = (layer == 0) ? x : &g_agg[layer - 1][0];
    const float* __restrict__ sc_base = g_scaleL + (layer - 1) * D;
    const float* __restrict__ sh_base = g_shiftL + (layer - 1) * D;

    __shared__ float As[2][16][128];
    __shared__ float Ws[2][16][128];

    const int tid  = threadIdx.x;
    const int brow = blockIdx.x * 128;
    const int tr   = (tid >> 4) * 8;
    const int tc   = (tid & 15) * 8;
    const int a_m  = tid >> 2;           // 0..63
    const int a_k4 = (tid & 3) * 4;      // 0,4,8,12
    const int w_k  = tid >> 5;           // 0..7
    const int w_n  = (tid & 31) * 4;

    float acc[8][8];
    #pragma unroll
    for (int i = 0; i < 8; i++)
        #pragma unroll
        for (int j = 0; j < 8; j++) acc[i][j] = 0.f;

    float4 va[2], vw[2];

    auto fetch = [&](int k0) {
        #pragma unroll
        for (int p = 0; p < 2; p++) {
            int gm = brow + a_m + p * 64;
            float4 v = make_float4(0.f, 0.f, 0.f, 0.f);
            if (gm < M) v = *(const float4*)(A + (long)gm * D + k0 + a_k4);
            va[p] = v;
            vw[p] = *(const float4*)(W + (k0 + w_k + p * 8) * D + w_n);
        }
        if (layer > 0) {
            float4 sc = *(const float4*)(sc_base + k0 + a_k4);
            float4 sh = *(const float4*)(sh_base + k0 + a_k4);
            #pragma unroll
            for (int p = 0; p < 2; p++) {
                va[p].x = fmaxf(0.f, fmaf(va[p].x, sc.x, sh.x));
                va[p].y = fmaxf(0.f, fmaf(va[p].y, sc.y, sh.y));
                va[p].z = fmaxf(0.f, fmaf(va[p].z, sc.z, sh.z));
                va[p].w = fmaxf(0.f, fmaf(va[p].w, sc.w, sh.w));
            }
        }
    };
    auto stage = [&](int buf) {
        #pragma unroll
        for (int p = 0; p < 2; p++) {
            int m = a_m + p * 64;
            As[buf][a_k4 + 0][m] = va[p].x;
            As[buf][a_k4 + 1][m] = va[p].y;
            As[buf][a_k4 + 2][m] = va[p].z;
            As[buf][a_k4 + 3][m] = va[p].w;
            *(float4*)&Ws[buf][w_k + p * 8][w_n] = vw[p];
        }
    };

    fetch(0);
    stage(0);
    __syncthreads();

    int buf = 0;
    for (int k0 = 16; k0 <= 128; k0 += 16) {
        const bool more = (k0 < 128);
        if (more) fetch(k0);
        #pragma unroll
        for (int k = 0; k < 16; k++) {
            float am[8], wn[8];
            #pragma unroll
            for (int i = 0; i < 8; i++) am[i] = As[buf][k][tr + i];
            #pragma unroll
            for (int j = 0; j < 8; j++) wn[j] = Ws[buf][k][tc + j];
            #pragma unroll
            for (int i = 0; i < 8; i++)
                #pragma unroll
                for (int j = 0; j < 8; j++)
                    acc[i][j] = fmaf(am[i], wn[j], acc[i][j]);
        }
        if (more) stage(buf ^ 1);
        __syncthreads();
        buf ^= 1;
    }

    #pragma unroll
    for (int i = 0; i < 8; i++) {
        int gm = brow + tr + i;
        if (gm < M) {
            #pragma unroll
            for (int j = 0; j < 8; j += 4)
                *(float4*)(g_hlin + (long)gm * D + tc + j) =
                    make_float4(acc[i][j], acc[i][j + 1], acc[i][j + 2], acc[i][j + 3]);
        }
    }
}

// ---------------- aggregation: agg = D^-1/2 (A+I) D^-1/2 hlin + b ----------
// warp per destination node, float4 per lane, 4 nodes per block
__global__ __launch_bounds__(128)
void agg_kernel(const float* __restrict__ b, int layer) {
    __shared__ int   sr[4][32];
    __shared__ float sd[4][32];
    const int g = threadIdx.x >> 5, lane = threadIdx.x & 31;
    const int c = blockIdx.x * 4 + g;
    if (c >= N_NODES) return;
    const float dc = g_dinv[c];
    const float4* __restrict__ hl = (const float4*)g_hlin;

    float4 acc = hl[(long)c * 32 + lane];   // self loop
    acc.x *= dc; acc.y *= dc; acc.z *= dc; acc.w *= dc;

    const int s = g_off[c], e = g_off[c + 1];
    for (int base = s; base < e; base += 32) {
        int idx = base + lane;
        if (idx < e) {
            int r = g_csr[idx];
            sr[g][lane] = r;
            sd[g][lane] = g_dinv[r];
        }
        __syncwarp();
        int cnt = min(32, e - base);
        int i = 0;
        for (; i + 4 <= cnt; i += 4) {
            int   r0 = sr[g][i],     r1 = sr[g][i + 1], r2 = sr[g][i + 2], r3 = sr[g][i + 3];
            float d0 = sd[g][i],     d1 = sd[g][i + 1], d2 = sd[g][i + 2], d3 = sd[g][i + 3];
            float4 v0 = hl[(long)r0 * 32 + lane];
            float4 v1 = hl[(long)r1 * 32 + lane];
            float4 v2 = hl[(long)r2 * 32 + lane];
            float4 v3 = hl[(long)r3 * 32 + lane];
            acc.x = fmaf(d0, v0.x, acc.x); acc.y = fmaf(d0, v0.y, acc.y);
            acc.z = fmaf(d0, v0.z, acc.z); acc.w = fmaf(d0, v0.w, acc.w);
            acc.x = fmaf(d1, v1.x, acc.x); acc.y = fmaf(d1, v1.y, acc.y);
            acc.z = fmaf(d1, v1.z, acc.z); acc.w = fmaf(d1, v1.w, acc.w);
            acc.x = fmaf(d2, v2.x, acc.x); acc.y = fmaf(d2, v2.y, acc.y);
            acc.z = fmaf(d2, v2.z, acc.z); acc.w = fmaf(d2, v2.w, acc.w);
            acc.x = fmaf(d3, v3.x, acc.x); acc.y = fmaf(d3, v3.y, acc.y);
            acc.z = fmaf(d3, v3.z, acc.z); acc.w = fmaf(d3, v3.w, acc.w);
        }
        for (; i < cnt; i++) {
            int r = sr[g][i]; float dv = sd[g][i];
            float4 v = hl[(long)r * 32 + lane];
            acc.x = fmaf(dv, v.x, acc.x); acc.y = fmaf(dv, v.y, acc.y);
            acc.z = fmaf(dv, v.z, acc.z); acc.w = fmaf(dv, v.w, acc.w);
        }
        __syncwarp();
    }
    float4 bb = ((const float4*)b)[lane];
    float4 o;
    o.x = fmaf(dc, acc.x, bb.x);
    o.y = fmaf(dc, acc.y, bb.y);
    o.z = fmaf(dc, acc.z, bb.z);
    o.w = fmaf(dc, acc.w, bb.w);
    ((float4*)&g_agg[layer][0])[(long)c * 32 + lane] = o;
}

// ---------------- batch norm stats ------------------------------------------
__global__ __launch_bounds__(512)
void bn_stats_kernel(int layer) {
    const float4* __restrict__ a = (const float4*)&g_agg[layer][0];
    const int w = threadIdx.x >> 5, lane = threadIdx.x & 31;
    const int gw = blockIdx.x * 16 + w;
    float4 s  = make_float4(0.f, 0.f, 0.f, 0.f);
    float4 s2 = make_float4(0.f, 0.f, 0.f, 0.f);
    for (int n = gw; n < N_NODES; n += NBS_WARPS) {
        float4 v = a[(long)n * 32 + lane];
        s.x += v.x;  s.y += v.y;  s.z += v.z;  s.w += v.w;
        s2.x = fmaf(v.x, v.x, s2.x); s2.y = fmaf(v.y, v.y, s2.y);
        s2.z = fmaf(v.z, v.z, s2.z); s2.w = fmaf(v.w, v.w, s2.w);
    }
    ((float4*)g_part )[(long)gw * 32 + lane] = s;
    ((float4*)g_part2)[(long)gw * 32 + lane] = s2;
}

__global__ __launch_bounds__(512)
void bn_finalize_kernel(const float* __restrict__ g,
                        const float* __restrict__ be, int layer) {
    __shared__ float ss[4][128], ss2[4][128];
    const int q = threadIdx.x >> 7, t = threadIdx.x & 127;
    float s = 0.f, s2 = 0.f;
    for (int i = q; i < NBS_WARPS; i += 4) {
        s  += g_part [i * D + t];
        s2 += g_part2[i * D + t];
    }
    ss[q][t] = s; ss2[q][t] = s2;
    __syncthreads();
    if (q == 0) {
        s  = ss [0][t] + ss [1][t] + ss [2][t] + ss [3][t];
        s2 = ss2[0][t] + ss2[1][t] + ss2[2][t] + ss2[3][t];
        float m   = s  / (float)N_NODES;
        float var = s2 / (float)N_NODES - m * m;
        float sc  = g[t] * rsqrtf(var + BN_EPS);
        g_scaleL[layer * D + t] = sc;
        g_shiftL[layer * D + t] = fmaf(-m, sc, be[t]);
    }
}

// ---------------- final: out = [relu(bn(agg0))|...|relu(bn(agg2))] @ Wf + bf
// warp per node, float4 lanes, shfl reduction
__global__ __launch_bounds__(256)
void final_kernel(const float* __restrict__ Wf, const float* __restrict__ bf,
                  float* __restrict__ out, int M) {
    __shared__ float wt[10][384];   // transposed Wf
    __shared__ float bfs[10];
    const int tid = threadIdx.x;
    for (int i = tid; i < 3840; i += 256) {
        int t = i / 10, c = i - t * 10;
        wt[c][t] = Wf[i];
    }
    if (tid < 10) bfs[tid] = bf[tid];
    __syncthreads();

    const int w = tid >> 5, lane = tid & 31;
    const int n = blockIdx.x * 8 + w;
    if (n >= M) return;

    float4 v[3];
    #pragma unroll
    for (int j = 0; j < 3; j++) {
        float4 a  = ((const float4*)&g_agg[j][0])[(long)n * 32 + lane];
        float4 sc = *(const float4*)(g_scaleL + j * D + lane * 4);
        float4 sh = *(const float4*)(g_shiftL + j * D + lane * 4);
        v[j].x = fmaxf(0.f, fmaf(a.x, sc.x, sh.x));
        v[j].y = fmaxf(0.f, fmaf(a.y, sc.y, sh.y));
        v[j].z = fmaxf(0.f, fmaf(a.z, sc.z, sh.z));
        v[j].w = fmaxf(0.f, fmaf(a.w, sc.w, sh.w));
    }

    float myout = 0.f;
    #pragma unroll
    for (int c = 0; c < 10; c++) {
        float s = 0.f;
        #pragma unroll
        for (int j = 0; j < 3; j++) {
            float4 wv = *(const float4*)&wt[c][j * 128 + lane * 4];
            s = fmaf(v[j].x, wv.x, s);
            s = fmaf(v[j].y, wv.y, s);
            s = fmaf(v[j].z, wv.z, s);
            s = fmaf(v[j].w, wv.w, s);
        }
        #pragma unroll
        for (int o = 16; o; o >>= 1) s += __shfl_xor_sync(0xffffffffu, s, o);
        if (lane == c) myout = s + bfs[c];
    }
    if (lane < 10) out[(long)n * 10 + lane] = myout;
}

// ---------------- launch -----------------------------------------------------
extern "C" void kernel_launch(void* const* d_in, const int* in_sizes, int n_in,
                              void* d_out, int out_size) {
    const float* x   = (const float*)d_in[0];
    const int*   ei  = (const int*)  d_in[1];
    const int    E   = in_sizes[1] / 2;
    const float* W1  = (const float*)d_in[2];
    const float* b1  = (const float*)d_in[3];
    const float* W2  = (const float*)d_in[4];
    const float* b2  = (const float*)d_in[5];
    const float* W3  = (const float*)d_in[6];
    const float* b3  = (const float*)d_in[7];
    const float* g1  = (const float*)d_in[8];
    const float* be1 = (const float*)d_in[9];
    const float* g2  = (const float*)d_in[10];
    const float* be2 = (const float*)d_in[11];
    const float* g3  = (const float*)d_in[12];
    const float* be3 = (const float*)d_in[13];
    const float* Wf  = (const float*)d_in[14];
    const float* bf  = (const float*)d_in[15];
    float* out = (float*)d_out;

    const int* row = ei;
    const int* col = ei + E;

    zero_init_kernel<<<(N_NODES + 255) / 256, 256>>>();
    hist_kernel<<<(E + 255) / 256, 256>>>(col, E);
    scan_kernel<<<1, 1024>>>(N_NODES);
    dinv_kernel<<<(N_NODES + 255) / 256, 256>>>();
    fill_csr_kernel<<<(E + 255) / 256, 256>>>(row, col, E);

    const int gemm_grid = (N_NODES + 127) / 128;
    const int agg_grid  = (N_NODES + 3) / 4;

    const float* Wl[3]  = {W1, W2, W3};
    const float* bl[3]  = {b1, b2, b3};
    const float* gl[3]  = {g1, g2, g3};
    const float* bel[3] = {be1, be2, be3};

    for (int l = 0; l < 3; l++) {
        sgemm_kernel<<<gemm_grid, 256>>>(x, Wl[l], l, N_NODES);
        agg_kernel<<<agg_grid, 128>>>(bl[l], l);
        bn_stats_kernel<<<NBS_BLK, 512>>>(l);
        bn_finalize_kernel<<<1, 512>>>(gl[l], bel[l], l);
    }

    final_kernel<<<(N_NODES + 7) / 8, 256>>>(Wf, bf, out, N_NODES);
}

// round 6
// speedup vs baseline: 1.8216x; 1.2372x over previous
#include <cuda_runtime.h>
#include <cuda_bf16.h>
#include <math.h>
#include <stdint.h>

#define N_NODES 50000
#define D 128
#define MAXE 800000
#define BN_EPS 1e-5f
#define NBS_BLK 120

// ---------------- scratch (device globals; no allocation allowed) ----------
__device__ float g_hlin[N_NODES * D];            // GEMM output (pre-aggregation)
__device__ float g_agg [3][N_NODES * D];         // raw conv outputs per layer
__device__ float g_dinv[N_NODES];
__device__ int   g_deg [N_NODES];
__device__ int   g_cur [N_NODES];
__device__ int   g_off [N_NODES + 1];
__device__ int   g_csr [MAXE];
__device__ float g_part [NBS_BLK * D];
__device__ float g_part2[NBS_BLK * D];
__device__ float g_scaleL[3 * D];
__device__ float g_shiftL[3 * D];
__device__ __nv_bfloat16 g_Bhi[3][D * D];        // W^T split hi (B[n][k] = W[k][n])
__device__ __nv_bfloat16 g_Blo[3][D * D];        // W^T split lo

// ---------------- helpers ----------------------------------------------------
__device__ __forceinline__ uint32_t smem_u32(const void* p) {
    uint32_t a;
    asm("{ .reg .u64 t; cvta.to.shared.u64 t, %1; cvt.u32.u64 %0, t; }" : "=r"(a) : "l"(p));
    return a;
}

#define LDSM_X4(r0, r1, r2, r3, addr) \
    asm volatile("ldmatrix.sync.aligned.m8n8.x4.shared.b16 {%0,%1,%2,%3}, [%4];" \
                 : "=r"(r0), "=r"(r1), "=r"(r2), "=r"(r3) : "r"(addr))

#define MMA_BF16(c, a, b0_, b1_) \
    asm volatile("mma.sync.aligned.m16n8k16.row.col.f32.bf16.bf16.f32 " \
                 "{%0,%1,%2,%3},{%4,%5,%6,%7},{%8,%9},{%0,%1,%2,%3};" \
                 : "+f"((c)[0]), "+f"((c)[1]), "+f"((c)[2]), "+f"((c)[3]) \
                 : "r"((a)[0]), "r"((a)[1]), "r"((a)[2]), "r"((a)[3]), \
                   "r"(b0_), "r"(b1_))

// ---------------- CSR build -------------------------------------------------
__global__ void zero_init_kernel() {
    int i = blockIdx.x * blockDim.x + threadIdx.x;
    if (i < N_NODES) { g_deg[i] = 0; g_cur[i] = 0; }
}

__global__ void hist_kernel(const int* __restrict__ col, int E) {
    int e = blockIdx.x * blockDim.x + threadIdx.x;
    if (e < E) atomicAdd(&g_deg[col[e]], 1);
}

__global__ void scan_kernel(int n) {   // also writes g_dinv
    __shared__ int wsum[32];
    const int tid = threadIdx.x;                 // 1024
    const int ipt = (n + 1023) >> 10;
    int start = tid * ipt;
    int end   = min(start + ipt, n);
    int s = 0;
    for (int i = start; i < end; i++) s += g_deg[i];
    int lane = tid & 31, w = tid >> 5;
    int v = s;
    #pragma unroll
    for (int d = 1; d < 32; d <<= 1) { int t = __shfl_up_sync(0xffffffffu, v, d); if (lane >= d) v += t; }
    if (lane == 31) wsum[w] = v;
    __syncthreads();
    if (w == 0) {
        int x = wsum[lane];
        #pragma unroll
        for (int d = 1; d < 32; d <<= 1) { int t = __shfl_up_sync(0xffffffffu, x, d); if (lane >= d) x += t; }
        wsum[lane] = x;
    }
    __syncthreads();
    int run = v - s + (w > 0 ? wsum[w - 1] : 0);
    for (int i = start; i < end; i++) {
        int dg = g_deg[i];
        g_off[i]  = run; run += dg;
        g_dinv[i] = rsqrtf((float)(dg + 1));
    }
    if (end == n) g_off[n] = run;
}

__global__ void fill_csr_kernel(const int* __restrict__ row,
                                const int* __restrict__ col, int E) {
    int e = blockIdx.x * blockDim.x + threadIdx.x;
    if (e < E) {
        int c = col[e];
        int p = atomicAdd(&g_cur[c], 1);
        g_csr[g_off[c] + p] = row[e];
    }
}

// ---------------- W split/transpose: B[n][k] = W[k][n] ----------------------
__global__ void convert_w_kernel(const float* __restrict__ W1,
                                 const float* __restrict__ W2,
                                 const float* __restrict__ W3) {
    const int l = blockIdx.y;
    const float* W = (l == 0) ? W1 : (l == 1) ? W2 : W3;
    const int n = blockIdx.x;            // 0..127
    const int k = threadIdx.x;           // 0..127
    float v = W[k * D + n];
    __nv_bfloat16 hi = __float2bfloat16_rn(v);
    __nv_bfloat16 lo = __float2bfloat16_rn(v - __bfloat162float(hi));
    g_Bhi[l][n * D + k] = hi;
    g_Blo[l][n * D + k] = lo;
}

// ---------------- HMMA GEMM: relu(bn(prev)) @ W -> g_hlin -------------------
// 128x128 tile per CTA; K processed in two 64-wide halves.
// smem per half: A_hi/A_lo/B_hi/B_lo, each 128 rows x 64 bf16 (128B rows, SW128).
// 8 warps = 4(M) x 2(N); per warp: 2 m16-atoms x 8 n8-atoms; 3 products.
#define GEMM_SMEM (65536 + 1024)

__global__ __launch_bounds__(256, 1)
void gemm_mma_kernel(const float* __restrict__ x, int layer, int M) {
    extern __shared__ char smem[];
    const uint32_t sa = smem_u32(smem);
    const uint32_t tb = (sa + 1023) & ~1023u;
    char* tbp = smem + (tb - sa);
    const uint32_t A_HI = tb, A_LO = tb + 16384, B_HI = tb + 32768, B_LO = tb + 49152;

    const int tid = threadIdx.x, wid = tid >> 5, lane = tid & 31;
    const int brow = blockIdx.x * 128;
    const int wm = wid & 3, wn = wid >> 2;

    const float* __restrict__ src = (layer == 0) ? x : &g_agg[layer - 1][0];
    const float4* __restrict__ scp = (const float4*)(g_scaleL + (layer > 0 ? (layer - 1) * D : 0));
    const float4* __restrict__ shp = (const float4*)(g_shiftL + (layer > 0 ? (layer - 1) * D : 0));
    const uint4* __restrict__ bhi_g = (const uint4*)&g_Bhi[layer][0];
    const uint4* __restrict__ blo_g = (const uint4*)&g_Blo[layer][0];

    // ---- fragment address precompute (row stride 128B, 8 chunks/row) ----
    const int g  = lane >> 3, lr = lane & 7;
    uint32_t a_rb[2]; int a_rm[2];
    const int a_kc = g >> 1;               // 0/1: k-chunk within k16 step
    #pragma unroll
    for (int a = 0; a < 2; a++) {
        int r = wm * 32 + a * 16 + (g & 1) * 8 + lr;
        a_rb[a] = (uint32_t)(r * 128);
        a_rm[a] = r & 7;
    }
    uint32_t b_rb[4]; int b_rm[4];
    const int b_kc = g & 1;
    #pragma unroll
    for (int b = 0; b < 4; b++) {
        int n = wn * 64 + b * 16 + (g >> 1) * 8 + lr;
        b_rb[b] = (uint32_t)(n * 128);
        b_rm[b] = n & 7;
    }

    float c[2][8][4];
    #pragma unroll
    for (int a = 0; a < 2; a++)
        #pragma unroll
        for (int j = 0; j < 8; j++)
            #pragma unroll
            for (int q = 0; q < 4; q++) c[a][j][q] = 0.f;

    for (int kh = 0; kh < 2; kh++) {
        // ---- load B half-tiles (128 n-rows x 8 chunks of 16B) ----
        for (int i = tid; i < 1024; i += 256) {
            int n = i >> 3, ck = i & 7;
            uint32_t off = (uint32_t)(n * 128 + ((ck ^ (n & 7)) << 4));
            int gi = n * 16 + kh * 8 + ck;
            *(uint4*)(tbp + 32768 + off) = bhi_g[gi];
            *(uint4*)(tbp + 49152 + off) = blo_g[gi];
        }
        // ---- load + convert A half-tile (128 rows x 16 float4) ----
        for (int i = tid; i < 2048; i += 256) {
            int r = i >> 4, cl = i & 15;          // local float4 col
            int cg = kh * 16 + cl;                // global float4 col
            int gm = brow + r;
            float4 v = make_float4(0.f, 0.f, 0.f, 0.f);
            if (gm < M) v = ((const float4*)(src + (long)gm * D))[cg];
            if (layer > 0) {
                float4 sc = scp[cg], sh = shp[cg];
                v.x = fmaxf(0.f, fmaf(v.x, sc.x, sh.x));
                v.y = fmaxf(0.f, fmaf(v.y, sc.y, sh.y));
                v.z = fmaxf(0.f, fmaf(v.z, sc.z, sh.z));
                v.w = fmaxf(0.f, fmaf(v.w, sc.w, sh.w));
            }
            __nv_bfloat16 hx = __float2bfloat16_rn(v.x), hy = __float2bfloat16_rn(v.y);
            __nv_bfloat16 hz = __float2bfloat16_rn(v.z), hw = __float2bfloat16_rn(v.w);
            __nv_bfloat16 lx = __float2bfloat16_rn(v.x - __bfloat162float(hx));
            __nv_bfloat16 ly = __float2bfloat16_rn(v.y - __bfloat162float(hy));
            __nv_bfloat16 lz = __float2bfloat16_rn(v.z - __bfloat162float(hz));
            __nv_bfloat16 lw = __float2bfloat16_rn(v.w - __bfloat162float(hw));
            __nv_bfloat162 h0 = __nv_bfloat162(hx, hy), h1 = __nv_bfloat162(hz, hw);
            __nv_bfloat162 l0 = __nv_bfloat162(lx, ly), l1 = __nv_bfloat162(lz, lw);
            uint2 hv, lv;
            hv.x = *(uint32_t*)&h0; hv.y = *(uint32_t*)&h1;
            lv.x = *(uint32_t*)&l0; lv.y = *(uint32_t*)&l1;
            uint32_t off = (uint32_t)(r * 128 + (((cl >> 1) ^ (r & 7)) << 4) + (cl & 1) * 8);
            *(uint2*)(tbp + off)         = hv;   // A_HI
            *(uint2*)(tbp + 16384 + off) = lv;   // A_LO
        }
        __syncthreads();

        // ---- 4 k16-steps over this half ----
        #pragma unroll
        for (int ks = 0; ks < 4; ks++) {
            const int ck = ks * 2;
            uint32_t ahi[2][4], alo[2][4], bhi[4][4], blo[4][4];
            #pragma unroll
            for (int a = 0; a < 2; a++) {
                uint32_t off = a_rb[a] + (uint32_t)((((ck + a_kc) ^ a_rm[a])) << 4);
                LDSM_X4(ahi[a][0], ahi[a][1], ahi[a][2], ahi[a][3], A_HI + off);
                LDSM_X4(alo[a][0], alo[a][1], alo[a][2], alo[a][3], A_LO + off);
            }
            #pragma unroll
            for (int b = 0; b < 4; b++) {
                uint32_t off = b_rb[b] + (uint32_t)((((ck + b_kc) ^ b_rm[b])) << 4);
                LDSM_X4(bhi[b][0], bhi[b][1], bhi[b][2], bhi[b][3], B_HI + off);
                LDSM_X4(blo[b][0], blo[b][1], blo[b][2], blo[b][3], B_LO + off);
            }
            #pragma unroll
            for (int a = 0; a < 2; a++)
                #pragma unroll
                for (int b = 0; b < 4; b++) {
                    MMA_BF16(c[a][b * 2],     ahi[a], bhi[b][0], bhi[b][1]);
                    MMA_BF16(c[a][b * 2 + 1], ahi[a], bhi[b][2], bhi[b][3]);
                    MMA_BF16(c[a][b * 2],     alo[a], bhi[b][0], bhi[b][1]);
                    MMA_BF16(c[a][b * 2 + 1], alo[a], bhi[b][2], bhi[b][3]);
                    MMA_BF16(c[a][b * 2],     ahi[a], blo[b][0], blo[b][1]);
                    MMA_BF16(c[a][b * 2 + 1], ahi[a], blo[b][2], blo[b][3]);
                }
        }
        __syncthreads();
    }

    // ---- epilogue: fragments -> g_hlin ----
    const int qr = lane >> 2, qc = lane & 3;
    #pragma unroll
    for (int a = 0; a < 2; a++) {
        int gr0 = brow + wm * 32 + a * 16 + qr;
        int gr1 = gr0 + 8;
        #pragma unroll
        for (int j = 0; j < 8; j++) {
            int col = wn * 64 + j * 8 + qc * 2;
            if (gr0 < M) *(float2*)(g_hlin + (long)gr0 * D + col) = make_float2(c[a][j][0], c[a][j][1]);
            if (gr1 < M) *(float2*)(g_hlin + (long)gr1 * D + col) = make_float2(c[a][j][2], c[a][j][3]);
        }
    }
}

// ---------------- aggregation -----------------------------------------------
__global__ __launch_bounds__(256)
void agg_kernel(const float* __restrict__ b, int layer) {
    __shared__ int   sr[8][32];
    __shared__ float sd[8][32];
    const int g = threadIdx.x >> 5, lane = threadIdx.x & 31;
    const int c = blockIdx.x * 8 + g;
    if (c >= N_NODES) return;
    const float dc = g_dinv[c];
    const float4* __restrict__ hl = (const float4*)g_hlin;

    float4 acc = hl[(long)c * 32 + lane];
    acc.x *= dc; acc.y *= dc; acc.z *= dc; acc.w *= dc;

    const int s = g_off[c], e = g_off[c + 1];
    for (int base = s; base < e; base += 32) {
        int idx = base + lane;
        if (idx < e) {
            int r = g_csr[idx];
            sr[g][lane] = r;
            sd[g][lane] = g_dinv[r];
        }
        __syncwarp();
        int cnt = min(32, e - base);
        int i = 0;
        for (; i + 4 <= cnt; i += 4) {
            int   r0 = sr[g][i], r1 = sr[g][i + 1], r2 = sr[g][i + 2], r3 = sr[g][i + 3];
            float d0 = sd[g][i], d1 = sd[g][i + 1], d2 = sd[g][i + 2], d3 = sd[g][i + 3];
            float4 v0 = hl[(long)r0 * 32 + lane];
            float4 v1 = hl[(long)r1 * 32 + lane];
            float4 v2 = hl[(long)r2 * 32 + lane];
            float4 v3 = hl[(long)r3 * 32 + lane];
            acc.x = fmaf(d0, v0.x, acc.x); acc.y = fmaf(d0, v0.y, acc.y);
            acc.z = fmaf(d0, v0.z, acc.z); acc.w = fmaf(d0, v0.w, acc.w);
            acc.x = fmaf(d1, v1.x, acc.x); acc.y = fmaf(d1, v1.y, acc.y);
            acc.z = fmaf(d1, v1.z, acc.z); acc.w = fmaf(d1, v1.w, acc.w);
            acc.x = fmaf(d2, v2.x, acc.x); acc.y = fmaf(d2, v2.y, acc.y);
            acc.z = fmaf(d2, v2.z, acc.z); acc.w = fmaf(d2, v2.w, acc.w);
            acc.x = fmaf(d3, v3.x, acc.x); acc.y = fmaf(d3, v3.y, acc.y);
            acc.z = fmaf(d3, v3.z, acc.z); acc.w = fmaf(d3, v3.w, acc.w);
        }
        for (; i < cnt; i++) {
            int r = sr[g][i]; float dv = sd[g][i];
            float4 v = hl[(long)r * 32 + lane];
            acc.x = fmaf(dv, v.x, acc.x); acc.y = fmaf(dv, v.y, acc.y);
            acc.z = fmaf(dv, v.z, acc.z); acc.w = fmaf(dv, v.w, acc.w);
        }
        __syncwarp();
    }
    float4 bb = ((const float4*)b)[lane];
    float4 o;
    o.x = fmaf(dc, acc.x, bb.x);
    o.y = fmaf(dc, acc.y, bb.y);
    o.z = fmaf(dc, acc.z, bb.z);
    o.w = fmaf(dc, acc.w, bb.w);
    ((float4*)&g_agg[layer][0])[(long)c * 32 + lane] = o;
}

// ---------------- batch norm ------------------------------------------------
__global__ __launch_bounds__(512)
void bn_stats_kernel(int layer) {
    __shared__ float ss [16][128];
    __shared__ float ss2[16][128];
    const float4* __restrict__ a = (const float4*)&g_agg[layer][0];
    const int w = threadIdx.x >> 5, lane = threadIdx.x & 31;
    const int gw = blockIdx.x * 16 + w;
    const int stride = NBS_BLK * 16;
    float4 s  = make_float4(0.f, 0.f, 0.f, 0.f);
    float4 s2 = make_float4(0.f, 0.f, 0.f, 0.f);
    for (int n = gw; n < N_NODES; n += stride) {
        float4 v = a[(long)n * 32 + lane];
        s.x += v.x;  s.y += v.y;  s.z += v.z;  s.w += v.w;
        s2.x = fmaf(v.x, v.x, s2.x); s2.y = fmaf(v.y, v.y, s2.y);
        s2.z = fmaf(v.z, v.z, s2.z); s2.w = fmaf(v.w, v.w, s2.w);
    }
    *(float4*)&ss [w][lane * 4] = s;
    *(float4*)&ss2[w][lane * 4] = s2;
    __syncthreads();
    if (threadIdx.x < 128) {
        const int t = threadIdx.x;
        float a1 = 0.f, a2 = 0.f;
        #pragma unroll
        for (int i = 0; i < 16; i++) { a1 += ss[i][t]; a2 += ss2[i][t]; }
        g_part [blockIdx.x * D + t] = a1;
        g_part2[blockIdx.x * D + t] = a2;
    }
}

__global__ __launch_bounds__(512)
void bn_finalize_kernel(const float* __restrict__ g,
                        const float* __restrict__ be, int layer) {
    __shared__ float ss[4][128], ss2[4][128];
    const int q = threadIdx.x >> 7, t = threadIdx.x & 127;
    float s = 0.f, s2 = 0.f;
    for (int i = q; i < NBS_BLK; i += 4) {
        s  += g_part [i * D + t];
        s2 += g_part2[i * D + t];
    }
    ss[q][t] = s; ss2[q][t] = s2;
    __syncthreads();
    if (q == 0) {
        s  = ss [0][t] + ss [1][t] + ss [2][t] + ss [3][t];
        s2 = ss2[0][t] + ss2[1][t] + ss2[2][t] + ss2[3][t];
        float m   = s  / (float)N_NODES;
        float var = s2 / (float)N_NODES - m * m;
        float sc  = g[t] * rsqrtf(var + BN_EPS);
        g_scaleL[layer * D + t] = sc;
        g_shiftL[layer * D + t] = fmaf(-m, sc, be[t]);
    }
}

// ---------------- final readout ---------------------------------------------
__global__ __launch_bounds__(256)
void final_kernel(const float* __restrict__ Wf, const float* __restrict__ bf,
                  float* __restrict__ out, int M) {
    __shared__ float wt[10][384];
    __shared__ float bfs[10];
    const int tid = threadIdx.x;
    for (int i = tid; i < 3840; i += 256) {
        int t = i / 10, c = i - t * 10;
        wt[c][t] = Wf[i];
    }
    if (tid < 10) bfs[tid] = bf[tid];
    __syncthreads();

    const int w = tid >> 5, lane = tid & 31;
    const int n = blockIdx.x * 8 + w;
    if (n >= M) return;

    float4 v[3];
    #pragma unroll
    for (int j = 0; j < 3; j++) {
        float4 a  = ((const float4*)&g_agg[j][0])[(long)n * 32 + lane];
        float4 sc = *(const float4*)(g_scaleL + j * D + lane * 4);
        float4 sh = *(const float4*)(g_shiftL + j * D + lane * 4);
        v[j].x = fmaxf(0.f, fmaf(a.x, sc.x, sh.x));
        v[j].y = fmaxf(0.f, fmaf(a.y, sc.y, sh.y));
        v[j].z = fmaxf(0.f, fmaf(a.z, sc.z, sh.z));
        v[j].w = fmaxf(0.f, fmaf(a.w, sc.w, sh.w));
    }

    float myout = 0.f;
    #pragma unroll
    for (int c = 0; c < 10; c++) {
        float s = 0.f;
        #pragma unroll
        for (int j = 0; j < 3; j++) {
            float4 wv = *(const float4*)&wt[c][j * 128 + lane * 4];
            s = fmaf(v[j].x, wv.x, s);
            s = fmaf(v[j].y, wv.y, s);
            s = fmaf(v[j].z, wv.z, s);
            s = fmaf(v[j].w, wv.w, s);
        }
        #pragma unroll
        for (int o = 16; o; o >>= 1) s += __shfl_xor_sync(0xffffffffu, s, o);
        if (lane == c) myout = s + bfs[c];
    }
    if (lane < 10) out[(long)n * 10 + lane] = myout;
}

// ---------------- launch -----------------------------------------------------
extern "C" void kernel_launch(void* const* d_in, const int* in_sizes, int n_in,
                              void* d_out, int out_size) {
    const float* x   = (const float*)d_in[0];
    const int*   ei  = (const int*)  d_in[1];
    const int    E   = in_sizes[1] / 2;
    const float* W1  = (const float*)d_in[2];
    const float* b1  = (const float*)d_in[3];
    const float* W2  = (const float*)d_in[4];
    const float* b2  = (const float*)d_in[5];
    const float* W3  = (const float*)d_in[6];
    const float* b3  = (const float*)d_in[7];
    const float* g1  = (const float*)d_in[8];
    const float* be1 = (const float*)d_in[9];
    const float* g2  = (const float*)d_in[10];
    const float* be2 = (const float*)d_in[11];
    const float* g3  = (const float*)d_in[12];
    const float* be3 = (const float*)d_in[13];
    const float* Wf  = (const float*)d_in[14];
    const float* bf  = (const float*)d_in[15];
    float* out = (float*)d_out;

    const int* row = ei;
    const int* col = ei + E;

    cudaFuncSetAttribute(gemm_mma_kernel,
                         cudaFuncAttributeMaxDynamicSharedMemorySize, GEMM_SMEM);

    zero_init_kernel<<<(N_NODES + 255) / 256, 256>>>();
    hist_kernel<<<(E + 255) / 256, 256>>>(col, E);
    scan_kernel<<<1, 1024>>>(N_NODES);
    fill_csr_kernel<<<(E + 255) / 256, 256>>>(row, col, E);
    convert_w_kernel<<<dim3(128, 3), 128>>>(W1, W2, W3);

    const int gemm_grid = (N_NODES + 127) / 128;
    const int agg_grid  = (N_NODES + 7) / 8;

    const float* bl[3]  = {b1, b2, b3};
    const float* gl[3]  = {g1, g2, g3};
    const float* bel[3] = {be1, be2, be3};

    for (int l = 0; l < 3; l++) {
        gemm_mma_kernel<<<gemm_grid, 256, GEMM_SMEM>>>(x, l, N_NODES);
        agg_kernel<<<agg_grid, 256>>>(bl[l], l);
        bn_stats_kernel<<<NBS_BLK, 512>>>(l);
        bn_finalize_kernel<<<1, 512>>>(gl[l], bel[l], l);
    }

    final_kernel<<<(N_NODES + 7) / 8, 256>>>(Wf, bf, out, N_NODES);
}

// round 7
// speedup vs baseline: 1.9272x; 1.0580x over previous
#include <cuda_runtime.h>
#include <cuda_bf16.h>
#include <cuda_fp16.h>
#include <math.h>
#include <stdint.h>

#define N_NODES 50000
#define D 128
#define MAXE 800000
#define BN_EPS 1e-5f
#define NBS_BLK 120

// ---------------- scratch (device globals; no allocation allowed) ----------
__device__ __half g_hlin_h[N_NODES * D];         // GEMM output (fp16, for gather)
__device__ float g_agg [3][N_NODES * D];         // raw conv outputs per layer
__device__ float g_dinv[N_NODES];
__device__ int   g_deg [N_NODES];
__device__ int   g_cur [N_NODES];
__device__ int   g_off [N_NODES + 1];
__device__ int   g_csr [MAXE];
__device__ float g_csrw[MAXE];                   // dinv[row] payload
__device__ float g_part [NBS_BLK * D];
__device__ float g_part2[NBS_BLK * D];
__device__ float g_scaleL[3 * D];
__device__ float g_shiftL[3 * D];
__device__ __nv_bfloat16 g_Bhi[3][D * D];        // W^T split hi (B[n][k] = W[k][n])
__device__ __nv_bfloat16 g_Blo[3][D * D];        // W^T split lo

// ---------------- helpers ----------------------------------------------------
__device__ __forceinline__ uint32_t smem_u32(const void* p) {
    uint32_t a;
    asm("{ .reg .u64 t; cvta.to.shared.u64 t, %1; cvt.u32.u64 %0, t; }" : "=r"(a) : "l"(p));
    return a;
}

#define LDSM_X4(r0, r1, r2, r3, addr) \
    asm volatile("ldmatrix.sync.aligned.m8n8.x4.shared.b16 {%0,%1,%2,%3}, [%4];" \
                 : "=r"(r0), "=r"(r1), "=r"(r2), "=r"(r3) : "r"(addr))

#define MMA_BF16(c, a, b0_, b1_) \
    asm volatile("mma.sync.aligned.m16n8k16.row.col.f32.bf16.bf16.f32 " \
                 "{%0,%1,%2,%3},{%4,%5,%6,%7},{%8,%9},{%0,%1,%2,%3};" \
                 : "+f"((c)[0]), "+f"((c)[1]), "+f"((c)[2]), "+f"((c)[3]) \
                 : "r"((a)[0]), "r"((a)[1]), "r"((a)[2]), "r"((a)[3]), \
                   "r"(b0_), "r"(b1_))

// ---------------- CSR build -------------------------------------------------
__global__ void zero_init_kernel() {
    int i = blockIdx.x * blockDim.x + threadIdx.x;
    if (i < N_NODES) { g_deg[i] = 0; g_cur[i] = 0; }
}

__global__ void hist_kernel(const int* __restrict__ col, int E) {
    int e = blockIdx.x * blockDim.x + threadIdx.x;
    if (e < E) atomicAdd(&g_deg[col[e]], 1);
}

__global__ void scan_kernel(int n) {   // also writes g_dinv
    __shared__ int wsum[32];
    const int tid = threadIdx.x;                 // 1024
    const int ipt = (n + 1023) >> 10;
    int start = tid * ipt;
    int end   = min(start + ipt, n);
    int s = 0;
    for (int i = start; i < end; i++) s += g_deg[i];
    int lane = tid & 31, w = tid >> 5;
    int v = s;
    #pragma unroll
    for (int d = 1; d < 32; d <<= 1) { int t = __shfl_up_sync(0xffffffffu, v, d); if (lane >= d) v += t; }
    if (lane == 31) wsum[w] = v;
    __syncthreads();
    if (w == 0) {
        int x = wsum[lane];
        #pragma unroll
        for (int d = 1; d < 32; d <<= 1) { int t = __shfl_up_sync(0xffffffffu, x, d); if (lane >= d) x += t; }
        wsum[lane] = x;
    }
    __syncthreads();
    int run = v - s + (w > 0 ? wsum[w - 1] : 0);
    for (int i = start; i < end; i++) {
        int dg = g_deg[i];
        g_off[i]  = run; run += dg;
        g_dinv[i] = rsqrtf((float)(dg + 1));
    }
    if (end == n) g_off[n] = run;
}

__global__ void fill_csr_kernel(const int* __restrict__ row,
                                const int* __restrict__ col, int E) {
    int e = blockIdx.x * blockDim.x + threadIdx.x;
    if (e < E) {
        int c = col[e];
        int r = row[e];
        int p = atomicAdd(&g_cur[c], 1);
        int slot = g_off[c] + p;
        g_csr [slot] = r;
        g_csrw[slot] = g_dinv[r];
    }
}

// ---------------- W split/transpose: B[n][k] = W[k][n] ----------------------
__global__ void convert_w_kernel(const float* __restrict__ W1,
                                 const float* __restrict__ W2,
                                 const float* __restrict__ W3) {
    const int l = blockIdx.y;
    const float* W = (l == 0) ? W1 : (l == 1) ? W2 : W3;
    const int n = blockIdx.x;            // 0..127
    const int k = threadIdx.x;           // 0..127
    float v = W[k * D + n];
    __nv_bfloat16 hi = __float2bfloat16_rn(v);
    __nv_bfloat16 lo = __float2bfloat16_rn(v - __bfloat162float(hi));
    g_Bhi[l][n * D + k] = hi;
    g_Blo[l][n * D + k] = lo;
}

// ---------------- HMMA GEMM: relu(bn(prev)) @ W -> g_hlin_h (fp16) ----------
// 128x128 tile per CTA; K processed in two 64-wide halves.
// smem per half: A_hi/A_lo/B_hi/B_lo, each 128 rows x 64 bf16 (128B rows, SW128).
// 8 warps = 4(M) x 2(N); per warp: 2 m16-atoms x 8 n8-atoms; 3 products.
#define GEMM_SMEM (65536 + 1024)

__global__ __launch_bounds__(256, 1)
void gemm_mma_kernel(const float* __restrict__ x, int layer, int M) {
    extern __shared__ char smem[];
    const uint32_t sa = smem_u32(smem);
    const uint32_t tb = (sa + 1023) & ~1023u;
    char* tbp = smem + (tb - sa);
    const uint32_t A_HI = tb, A_LO = tb + 16384, B_HI = tb + 32768, B_LO = tb + 49152;

    const int tid = threadIdx.x, wid = tid >> 5, lane = tid & 31;
    const int brow = blockIdx.x * 128;
    const int wm = wid & 3, wn = wid >> 2;

    const float* __restrict__ src = (layer == 0) ? x : &g_agg[layer - 1][0];
    const float4* __restrict__ scp = (const float4*)(g_scaleL + (layer > 0 ? (layer - 1) * D : 0));
    const float4* __restrict__ shp = (const float4*)(g_shiftL + (layer > 0 ? (layer - 1) * D : 0));
    const uint4* __restrict__ bhi_g = (const uint4*)&g_Bhi[layer][0];
    const uint4* __restrict__ blo_g = (const uint4*)&g_Blo[layer][0];

    // ---- fragment address precompute (row stride 128B, 8 chunks/row) ----
    const int g  = lane >> 3, lr = lane & 7;
    uint32_t a_rb[2]; int a_rm[2];
    const int a_kc = g >> 1;               // 0/1: k-chunk within k16 step
    #pragma unroll
    for (int a = 0; a < 2; a++) {
        int r = wm * 32 + a * 16 + (g & 1) * 8 + lr;
        a_rb[a] = (uint32_t)(r * 128);
        a_rm[a] = r & 7;
    }
    uint32_t b_rb[4]; int b_rm[4];
    const int b_kc = g & 1;
    #pragma unroll
    for (int b = 0; b < 4; b++) {
        int n = wn * 64 + b * 16 + (g >> 1) * 8 + lr;
        b_rb[b] = (uint32_t)(n * 128);
        b_rm[b] = n & 7;
    }

    float c[2][8][4];
    #pragma unroll
    for (int a = 0; a < 2; a++)
        #pragma unroll
        for (int j = 0; j < 8; j++)
            #pragma unroll
            for (int q = 0; q < 4; q++) c[a][j][q] = 0.f;

    for (int kh = 0; kh < 2; kh++) {
        // ---- load B half-tiles (128 n-rows x 8 chunks of 16B) ----
        for (int i = tid; i < 1024; i += 256) {
            int n = i >> 3, ck = i & 7;
            uint32_t off = (uint32_t)(n * 128 + ((ck ^ (n & 7)) << 4));
            int gi = n * 16 + kh * 8 + ck;
            *(uint4*)(tbp + 32768 + off) = bhi_g[gi];
            *(uint4*)(tbp + 49152 + off) = blo_g[gi];
        }
        // ---- load + convert A half-tile (128 rows x 16 float4) ----
        for (int i = tid; i < 2048; i += 256) {
            int r = i >> 4, cl = i & 15;          // local float4 col
            int cg = kh * 16 + cl;                // global float4 col
            int gm = brow + r;
            float4 v = make_float4(0.f, 0.f, 0.f, 0.f);
            if (gm < M) v = ((const float4*)(src + (long)gm * D))[cg];
            if (layer > 0) {
                float4 sc = scp[cg], sh = shp[cg];
                v.x = fmaxf(0.f, fmaf(v.x, sc.x, sh.x));
                v.y = fmaxf(0.f, fmaf(v.y, sc.y, sh.y));
                v.z = fmaxf(0.f, fmaf(v.z, sc.z, sh.z));
                v.w = fmaxf(0.f, fmaf(v.w, sc.w, sh.w));
            }
            __nv_bfloat16 hx = __float2bfloat16_rn(v.x), hy = __float2bfloat16_rn(v.y);
            __nv_bfloat16 hz = __float2bfloat16_rn(v.z), hw = __float2bfloat16_rn(v.w);
            __nv_bfloat16 lx = __float2bfloat16_rn(v.x - __bfloat162float(hx));
            __nv_bfloat16 ly = __float2bfloat16_rn(v.y - __bfloat162float(hy));
            __nv_bfloat16 lz = __float2bfloat16_rn(v.z - __bfloat162float(hz));
            __nv_bfloat16 lw = __float2bfloat16_rn(v.w - __bfloat162float(hw));
            __nv_bfloat162 h0 = __nv_bfloat162(hx, hy), h1 = __nv_bfloat162(hz, hw);
            __nv_bfloat162 l0 = __nv_bfloat162(lx, ly), l1 = __nv_bfloat162(lz, lw);
            uint2 hv, lv;
            hv.x = *(uint32_t*)&h0; hv.y = *(uint32_t*)&h1;
            lv.x = *(uint32_t*)&l0; lv.y = *(uint32_t*)&l1;
            uint32_t off = (uint32_t)(r * 128 + (((cl >> 1) ^ (r & 7)) << 4) + (cl & 1) * 8);
            *(uint2*)(tbp + off)         = hv;   // A_HI
            *(uint2*)(tbp + 16384 + off) = lv;   // A_LO
        }
        __syncthreads();

        // ---- 4 k16-steps over this half ----
        #pragma unroll
        for (int ks = 0; ks < 4; ks++) {
            const int ck = ks * 2;
            uint32_t ahi[2][4], alo[2][4], bhi[4][4], blo[4][4];
            #pragma unroll
            for (int a = 0; a < 2; a++) {
                uint32_t off = a_rb[a] + (uint32_t)((((ck + a_kc) ^ a_rm[a])) << 4);
                LDSM_X4(ahi[a][0], ahi[a][1], ahi[a][2], ahi[a][3], A_HI + off);
                LDSM_X4(alo[a][0], alo[a][1], alo[a][2], alo[a][3], A_LO + off);
            }
            #pragma unroll
            for (int b = 0; b < 4; b++) {
                uint32_t off = b_rb[b] + (uint32_t)((((ck + b_kc) ^ b_rm[b])) << 4);
                LDSM_X4(bhi[b][0], bhi[b][1], bhi[b][2], bhi[b][3], B_HI + off);
                LDSM_X4(blo[b][0], blo[b][1], blo[b][2], blo[b][3], B_LO + off);
            }
            #pragma unroll
            for (int a = 0; a < 2; a++)
                #pragma unroll
                for (int b = 0; b < 4; b++) {
                    MMA_BF16(c[a][b * 2],     ahi[a], bhi[b][0], bhi[b][1]);
                    MMA_BF16(c[a][b * 2 + 1], ahi[a], bhi[b][2], bhi[b][3]);
                    MMA_BF16(c[a][b * 2],     alo[a], bhi[b][0], bhi[b][1]);
                    MMA_BF16(c[a][b * 2 + 1], alo[a], bhi[b][2], bhi[b][3]);
                    MMA_BF16(c[a][b * 2],     ahi[a], blo[b][0], blo[b][1]);
                    MMA_BF16(c[a][b * 2 + 1], ahi[a], blo[b][2], blo[b][3]);
                }
        }
        __syncthreads();
    }

    // ---- epilogue: fragments -> g_hlin_h (fp16) ----
    const int qr = lane >> 2, qc = lane & 3;
    #pragma unroll
    for (int a = 0; a < 2; a++) {
        int gr0 = brow + wm * 32 + a * 16 + qr;
        int gr1 = gr0 + 8;
        #pragma unroll
        for (int j = 0; j < 8; j++) {
            int col = wn * 64 + j * 8 + qc * 2;
            if (gr0 < M)
                *(__half2*)(g_hlin_h + (long)gr0 * D + col) = __floats2half2_rn(c[a][j][0], c[a][j][1]);
            if (gr1 < M)
                *(__half2*)(g_hlin_h + (long)gr1 * D + col) = __floats2half2_rn(c[a][j][2], c[a][j][3]);
        }
    }
}

// ---------------- aggregation (fp16 gather, fp32 accumulate) ----------------
// warp per destination node; lane covers 4 features via uint2 (4 halfs)
__global__ __launch_bounds__(256)
void agg_kernel(const float* __restrict__ b, int layer) {
    __shared__ int   sr[8][32];
    __shared__ float sd[8][32];
    const int g = threadIdx.x >> 5, lane = threadIdx.x & 31;
    const int c = blockIdx.x * 8 + g;
    if (c >= N_NODES) return;
    const float dc = g_dinv[c];
    const uint2* __restrict__ hl = (const uint2*)g_hlin_h;   // row = 32 uint2

    auto cvt = [](uint2 u, float4& f) {
        __half2 p0 = *(__half2*)&u.x, p1 = *(__half2*)&u.y;
        float2 a0 = __half22float2(p0), a1 = __half22float2(p1);
        f.x = a0.x; f.y = a0.y; f.z = a1.x; f.w = a1.y;
    };

    float4 self; cvt(hl[(long)c * 32 + lane], self);
    float4 acc = make_float4(self.x * dc, self.y * dc, self.z * dc, self.w * dc);

    const int s = g_off[c], e = g_off[c + 1];
    for (int base = s; base < e; base += 32) {
        int idx = base + lane;
        if (idx < e) {
            sr[g][lane] = g_csr [idx];
            sd[g][lane] = g_csrw[idx];
        }
        __syncwarp();
        int cnt = min(32, e - base);
        int i = 0;
        for (; i + 4 <= cnt; i += 4) {
            int   r0 = sr[g][i], r1 = sr[g][i + 1], r2 = sr[g][i + 2], r3 = sr[g][i + 3];
            float d0 = sd[g][i], d1 = sd[g][i + 1], d2 = sd[g][i + 2], d3 = sd[g][i + 3];
            uint2 u0 = hl[(long)r0 * 32 + lane];
            uint2 u1 = hl[(long)r1 * 32 + lane];
            uint2 u2 = hl[(long)r2 * 32 + lane];
            uint2 u3 = hl[(long)r3 * 32 + lane];
            float4 v0, v1, v2, v3;
            cvt(u0, v0); cvt(u1, v1); cvt(u2, v2); cvt(u3, v3);
            acc.x = fmaf(d0, v0.x, acc.x); acc.y = fmaf(d0, v0.y, acc.y);
            acc.z = fmaf(d0, v0.z, acc.z); acc.w = fmaf(d0, v0.w, acc.w);
            acc.x = fmaf(d1, v1.x, acc.x); acc.y = fmaf(d1, v1.y, acc.y);
            acc.z = fmaf(d1, v1.z, acc.z); acc.w = fmaf(d1, v1.w, acc.w);
            acc.x = fmaf(d2, v2.x, acc.x); acc.y = fmaf(d2, v2.y, acc.y);
            acc.z = fmaf(d2, v2.z, acc.z); acc.w = fmaf(d2, v2.w, acc.w);
            acc.x = fmaf(d3, v3.x, acc.x); acc.y = fmaf(d3, v3.y, acc.y);
            acc.z = fmaf(d3, v3.z, acc.z); acc.w = fmaf(d3, v3.w, acc.w);
        }
        for (; i < cnt; i++) {
            int r = sr[g][i]; float dv = sd[g][i];
            float4 v; cvt(hl[(long)r * 32 + lane], v);
            acc.x = fmaf(dv, v.x, acc.x); acc.y = fmaf(dv, v.y, acc.y);
            acc.z = fmaf(dv, v.z, acc.z); acc.w = fmaf(dv, v.w, acc.w);
        }
        __syncwarp();
    }
    float4 bb = ((const float4*)b)[lane];
    float4 o;
    o.x = fmaf(dc, acc.x, bb.x);
    o.y = fmaf(dc, acc.y, bb.y);
    o.z = fmaf(dc, acc.z, bb.z);
    o.w = fmaf(dc, acc.w, bb.w);
    ((float4*)&g_agg[layer][0])[(long)c * 32 + lane] = o;
}

// ---------------- batch norm ------------------------------------------------
__global__ __launch_bounds__(512)
void bn_stats_kernel(int layer) {
    __shared__ float ss [16][128];
    __shared__ float ss2[16][128];
    const float4* __restrict__ a = (const float4*)&g_agg[layer][0];
    const int w = threadIdx.x >> 5, lane = threadIdx.x & 31;
    const int gw = blockIdx.x * 16 + w;
    const int stride = NBS_BLK * 16;
    float4 s  = make_float4(0.f, 0.f, 0.f, 0.f);
    float4 s2 = make_float4(0.f, 0.f, 0.f, 0.f);
    for (int n = gw; n < N_NODES; n += stride) {
        float4 v = a[(long)n * 32 + lane];
        s.x += v.x;  s.y += v.y;  s.z += v.z;  s.w += v.w;
        s2.x = fmaf(v.x, v.x, s2.x); s2.y = fmaf(v.y, v.y, s2.y);
        s2.z = fmaf(v.z, v.z, s2.z); s2.w = fmaf(v.w, v.w, s2.w);
    }
    *(float4*)&ss [w][lane * 4] = s;
    *(float4*)&ss2[w][lane * 4] = s2;
    __syncthreads();
    if (threadIdx.x < 128) {
        const int t = threadIdx.x;
        float a1 = 0.f, a2 = 0.f;
        #pragma unroll
        for (int i = 0; i < 16; i++) { a1 += ss[i][t]; a2 += ss2[i][t]; }
        g_part [blockIdx.x * D + t] = a1;
        g_part2[blockIdx.x * D + t] = a2;
    }
}

__global__ __launch_bounds__(512)
void bn_finalize_kernel(const float* __restrict__ g,
                        const float* __restrict__ be, int layer) {
    __shared__ float ss[4][128], ss2[4][128];
    const int q = threadIdx.x >> 7, t = threadIdx.x & 127;
    float s = 0.f, s2 = 0.f;
    for (int i = q; i < NBS_BLK; i += 4) {
        s  += g_part [i * D + t];
        s2 += g_part2[i * D + t];
    }
    ss[q][t] = s; ss2[q][t] = s2;
    __syncthreads();
    if (q == 0) {
        s  = ss [0][t] + ss [1][t] + ss [2][t] + ss [3][t];
        s2 = ss2[0][t] + ss2[1][t] + ss2[2][t] + ss2[3][t];
        float m   = s  / (float)N_NODES;
        float var = s2 / (float)N_NODES - m * m;
        float sc  = g[t] * rsqrtf(var + BN_EPS);
        g_scaleL[layer * D + t] = sc;
        g_shiftL[layer * D + t] = fmaf(-m, sc, be[t]);
    }
}

// ---------------- final readout ---------------------------------------------
__global__ __launch_bounds__(256)
void final_kernel(const float* __restrict__ Wf, const float* __restrict__ bf,
                  float* __restrict__ out, int M) {
    __shared__ float wt[10][384];
    __shared__ float bfs[10];
    const int tid = threadIdx.x;
    for (int i = tid; i < 3840; i += 256) {
        int t = i / 10, c = i - t * 10;
        wt[c][t] = Wf[i];
    }
    if (tid < 10) bfs[tid] = bf[tid];
    __syncthreads();

    const int w = tid >> 5, lane = tid & 31;
    const int n = blockIdx.x * 8 + w;
    if (n >= M) return;

    float4 v[3];
    #pragma unroll
    for (int j = 0; j < 3; j++) {
        float4 a  = ((const float4*)&g_agg[j][0])[(long)n * 32 + lane];
        float4 sc = *(const float4*)(g_scaleL + j * D + lane * 4);
        float4 sh = *(const float4*)(g_shiftL + j * D + lane * 4);
        v[j].x = fmaxf(0.f, fmaf(a.x, sc.x, sh.x));
        v[j].y = fmaxf(0.f, fmaf(a.y, sc.y, sh.y));
        v[j].z = fmaxf(0.f, fmaf(a.z, sc.z, sh.z));
        v[j].w = fmaxf(0.f, fmaf(a.w, sc.w, sh.w));
    }

    float myout = 0.f;
    #pragma unroll
    for (int c = 0; c < 10; c++) {
        float s = 0.f;
        #pragma unroll
        for (int j = 0; j < 3; j++) {
            float4 wv = *(const float4*)&wt[c][j * 128 + lane * 4];
            s = fmaf(v[j].x, wv.x, s);
            s = fmaf(v[j].y, wv.y, s);
            s = fmaf(v[j].z, wv.z, s);
            s = fmaf(v[j].w, wv.w, s);
        }
        #pragma unroll
        for (int o = 16; o; o >>= 1) s += __shfl_xor_sync(0xffffffffu, s, o);
        if (lane == c) myout = s + bfs[c];
    }
    if (lane < 10) out[(long)n * 10 + lane] = myout;
}

// ---------------- launch -----------------------------------------------------
extern "C" void kernel_launch(void* const* d_in, const int* in_sizes, int n_in,
                              void* d_out, int out_size) {
    const float* x   = (const float*)d_in[0];
    const int*   ei  = (const int*)  d_in[1];
    const int    E   = in_sizes[1] / 2;
    const float* W1  = (const float*)d_in[2];
    const float* b1  = (const float*)d_in[3];
    const float* W2  = (const float*)d_in[4];
    const float* b2  = (const float*)d_in[5];
    const float* W3  = (const float*)d_in[6];
    const float* b3  = (const float*)d_in[7];
    const float* g1  = (const float*)d_in[8];
    const float* be1 = (const float*)d_in[9];
    const float* g2  = (const float*)d_in[10];
    const float* be2 = (const float*)d_in[11];
    const float* g3  = (const float*)d_in[12];
    const float* be3 = (const float*)d_in[13];
    const float* Wf  = (const float*)d_in[14];
    const float* bf  = (const float*)d_in[15];
    float* out = (float*)d_out;

    const int* row = ei;
    const int* col = ei + E;

    cudaFuncSetAttribute(gemm_mma_kernel,
                         cudaFuncAttributeMaxDynamicSharedMemorySize, GEMM_SMEM);

    zero_init_kernel<<<(N_NODES + 255) / 256, 256>>>();
    hist_kernel<<<(E + 255) / 256, 256>>>(col, E);
    scan_kernel<<<1, 1024>>>(N_NODES);
    fill_csr_kernel<<<(E + 255) / 256, 256>>>(row, col, E);
    convert_w_kernel<<<dim3(128, 3), 128>>>(W1, W2, W3);

    const int gemm_grid = (N_NODES + 127) / 128;
    const int agg_grid  = (N_NODES + 7) / 8;

    const float* bl[3]  = {b1, b2, b3};
    const float* gl[3]  = {g1, g2, g3};
    const float* bel[3] = {be1, be2, be3};

    for (int l = 0; l < 3; l++) {
        gemm_mma_kernel<<<gemm_grid, 256, GEMM_SMEM>>>(x, l, N_NODES);
        agg_kernel<<<agg_grid, 256>>>(bl[l], l);
        bn_stats_kernel<<<NBS_BLK, 512>>>(l);
        bn_finalize_kernel<<<1, 512>>>(gl[l], bel[l], l);
    }

    final_kernel<<<(N_NODES + 7) / 8, 256>>>(Wf, bf, out, N_NODES);
}